// round 5
// baseline (speedup 1.0000x reference)
#include <cuda_runtime.h>
#include <cuda_bf16.h>
#include <math_constants.h>

// ============================================================================
// CosineVectorQuantizer on GB300 (sm_103a)
//
//   x:         (B=32768, D=256) fp32
//   embedding: (N=8192,  D=256) fp32
//   outputs (flattened fp32, tuple order, written as far as out_size reaches):
//     x_q (B*D) | loss (1) | indices (B) | scalar (B)
//
// Pipeline:
//   k_rnorm        : rnorm[n] = 1/max(||e_n||, 1e-12)
//   k_gemm_argmax  : fused fp32 GEMM (packed fma.rn.f32x2, K-paired
//                    accumulators) + per-row argmax of (x.e_n)*rnorm[n]
//                    (identical argmax to the reference's argmin over
//                     1 - cos since ||x|| > 0 is row-constant; ties -> low n)
//   k_epilogue     : per-row gather e[idx], scalar projection, x_q, scalar,
//                    per-block partial of (1 - cosine(proj, x))
//   k_loss         : deterministic final reduction -> loss
// ============================================================================

#define Bsz 32768
#define Dsz 256
#define Nsz 8192

#define BM 64            // rows per block tile
#define BN 128           // codes per n-chunk
#define KB 32            // k-depth per smem stage
#define NC (Nsz / BN)    // 64 n-chunks
#define KC (Dsz / KB)    // 8  k-chunks

#define XS_STRIDE 260                    // 256 + 4 pad (16B-aligned rows, no bank conflicts)
#define ES_STRIDE 36                     // 32 + 4 pad  (144B row stride, 16B aligned)
#define XS_FLOATS (BM * XS_STRIDE)       // 16640
#define ES_BUF    (BN * ES_STRIDE)       // 4608
#define ES_FLOATS (2 * ES_BUF)           // 9216
#define SMEM_FLOATS (XS_FLOATS + ES_FLOATS + BN)
#define SMEM_BYTES  (SMEM_FLOATS * 4)    // 103,936 B

// -------- device scratch (no dynamic allocations allowed) --------
__device__ float g_rnorm[Nsz];
__device__ int   g_idx[Bsz];
__device__ float g_partial[Bsz / 8];     // 4096 per-block loss partials

// packed fp32 FMA: d.lo = a.lo*b.lo + c.lo ; d.hi = a.hi*b.hi + c.hi
__device__ __forceinline__ unsigned long long ffma2(unsigned long long a,
                                                    unsigned long long b,
                                                    unsigned long long c) {
    unsigned long long d;
    asm("fma.rn.f32x2 %0, %1, %2, %3;" : "=l"(d) : "l"(a), "l"(b), "l"(c));
    return d;
}

// ============================================================================
// Kernel A: codebook inverse norms
// ============================================================================
__global__ void k_rnorm(const float* __restrict__ E) {
    int wid = threadIdx.x >> 5, lane = threadIdx.x & 31;
    int n = blockIdx.x * 8 + wid;
    const float4* e = (const float4*)(E + (size_t)n * Dsz);
    float4 v1 = e[lane];
    float4 v2 = e[lane + 32];
    float ss = v1.x*v1.x + v1.y*v1.y + v1.z*v1.z + v1.w*v1.w
             + v2.x*v2.x + v2.y*v2.y + v2.z*v2.z + v2.w*v2.w;
#pragma unroll
    for (int o = 16; o; o >>= 1) ss += __shfl_xor_sync(0xffffffffu, ss, o);
    if (lane == 0) g_rnorm[n] = 1.0f / fmaxf(sqrtf(ss), 1e-12f);
}

// ============================================================================
// Kernel B: fused GEMM + argmax
// ============================================================================
__device__ __forceinline__ void b_stage_ld(const float* __restrict__ E, int n0, int kc,
                                           float4* pf, int tid) {
#pragma unroll
    for (int s = 0; s < 4; s++) {
        int lin = tid + s * 256;          // 0..1023 float4s of the 128x32 tile
        int row = lin >> 3;               // 0..127
        int c4  = lin & 7;                // 0..7
        pf[s] = *(const float4*)(E + (size_t)(n0 + row) * Dsz + kc * KB + c4 * 4);
    }
}

__device__ __forceinline__ void b_stage_st(float* __restrict__ Eb, const float4* pf, int tid) {
#pragma unroll
    for (int s = 0; s < 4; s++) {
        int lin = tid + s * 256;
        int row = lin >> 3;
        int c4  = lin & 7;
        *(float4*)(Eb + row * ES_STRIDE + c4 * 4) = pf[s];
    }
}

__device__ __forceinline__ void b_compute(const float* __restrict__ Xs,
                                          const float* __restrict__ Eb,
                                          int kc, int tx, int ty,
                                          unsigned long long acc[4][8]) {
#pragma unroll
    for (int k4 = 0; k4 < KB; k4 += 4) {
        unsigned long long a01[4], a23[4];
#pragma unroll
        for (int i = 0; i < 4; i++) {
            // 16B aligned: XS_STRIDE*4 = 1040 (mult of 16), k offsets mult of 16
            ulonglong2 av = *(const ulonglong2*)(Xs + (ty * 4 + i) * XS_STRIDE + kc * KB + k4);
            a01[i] = av.x;   // (x[r][k4],   x[r][k4+1])
            a23[i] = av.y;   // (x[r][k4+2], x[r][k4+3])
        }
#pragma unroll
        for (int j = 0; j < 8; j++) {
            ulonglong2 bv = *(const ulonglong2*)(Eb + (tx + 16 * j) * ES_STRIDE + k4);
#pragma unroll
            for (int i = 0; i < 4; i++) {
                acc[i][j] = ffma2(a01[i], bv.x, acc[i][j]);   // even-k in .lo, odd-k in .hi
                acc[i][j] = ffma2(a23[i], bv.y, acc[i][j]);
            }
        }
    }
}

__global__ void __launch_bounds__(256, 1)
k_gemm_argmax(const float* __restrict__ X, const float* __restrict__ E,
              float* __restrict__ out_idx, int w_idx) {
    extern __shared__ float sm[];
    float* Xs  = sm;                      // [BM][XS_STRIDE]
    float* Es  = sm + XS_FLOATS;          // [2][BN][ES_STRIDE]
    float* rns = Es + ES_FLOATS;          // [BN]

    int tid = threadIdx.x;
    int tx = tid & 15, ty = tid >> 4;
    int b0 = blockIdx.x * BM;

    // Stage the full X tile (64 x 256) once; coalesced 16B loads.
#pragma unroll
    for (int s = 0; s < 16; s++) {
        int lin = tid + s * 256;
        int row = lin >> 6, c4 = lin & 63;
        *(float4*)(Xs + row * XS_STRIDE + c4 * 4) =
            *(const float4*)(X + (size_t)(b0 + row) * Dsz + c4 * 4);
    }

    float best[4];
    int   bidx[4];
#pragma unroll
    for (int i = 0; i < 4; i++) { best[i] = -CUDART_INF_F; bidx[i] = 0; }

#pragma unroll 1
    for (int nc = 0; nc < NC; nc++) {
        int n0 = nc * BN;
        __syncthreads();                               // protect Es/rns reuse (and Xs on nc==0)
        if (tid < BN) rns[tid] = g_rnorm[n0 + tid];
        {
            float4 pf[4];
            b_stage_ld(E, n0, 0, pf, tid);
            b_stage_st(Es, pf, tid);
        }
        __syncthreads();

        unsigned long long acc[4][8];
#pragma unroll
        for (int i = 0; i < 4; i++)
#pragma unroll
            for (int j = 0; j < 8; j++) acc[i][j] = 0ULL;

        int buf = 0;
#pragma unroll 1
        for (int kc = 0; kc < KC; kc++) {
            float4 pf[4];
            if (kc + 1 < KC) b_stage_ld(E, n0, kc + 1, pf, tid);  // prefetch into regs
            b_compute(Xs, Es + buf * ES_BUF, kc, tx, ty, acc);
            if (kc + 1 < KC) {
                __syncthreads();
                b_stage_st(Es + (buf ^ 1) * ES_BUF, pf, tid);
                buf ^= 1;
                __syncthreads();
            }
        }

        // fold packed accumulators -> scores; running argmax (ties -> smaller n)
#pragma unroll
        for (int j = 0; j < 8; j++) {
            int nl = tx + 16 * j;
            float rn = rns[nl];
            int gn = n0 + nl;
#pragma unroll
            for (int i = 0; i < 4; i++) {
                unsigned long long v = acc[i][j];
                float lo = __uint_as_float((unsigned)v);
                float hi = __uint_as_float((unsigned)(v >> 32));
                float s = (lo + hi) * rn;
                if (s > best[i] || (s == best[i] && gn < bidx[i])) { best[i] = s; bidx[i] = gn; }
            }
        }
    }

    // cross-thread reduction over the 16 tx lanes sharing each row
#pragma unroll
    for (int i = 0; i < 4; i++) {
        float s = best[i];
        int   id = bidx[i];
#pragma unroll
        for (int o = 8; o >= 1; o >>= 1) {
            float s2 = __shfl_xor_sync(0xffffffffu, s, o);
            int   i2 = __shfl_xor_sync(0xffffffffu, id, o);
            if (s2 > s || (s2 == s && i2 < id)) { s = s2; id = i2; }
        }
        if (tx == 0) {
            int b = b0 + ty * 4 + i;
            g_idx[b] = id;
            if (w_idx) out_idx[b] = (float)id;
        }
    }
}

// ============================================================================
// Kernel C: per-row projection epilogue (warp per row)
// ============================================================================
__global__ void k_epilogue(const float* __restrict__ X, const float* __restrict__ E,
                           float* __restrict__ xq, float* __restrict__ out_sca, int w_sca) {
    __shared__ float part[8];
    int w = threadIdx.x >> 5, lane = threadIdx.x & 31;
    int b = blockIdx.x * 8 + w;
    int idx = g_idx[b];

    const float4* xv = (const float4*)(X + (size_t)b   * Dsz);
    const float4* ev = (const float4*)(E + (size_t)idx * Dsz);
    float4 x1 = xv[lane], x2 = xv[lane + 32];
    float4 e1 = ev[lane], e2 = ev[lane + 32];

    float dot = x1.x*e1.x + x1.y*e1.y + x1.z*e1.z + x1.w*e1.w
              + x2.x*e2.x + x2.y*e2.y + x2.z*e2.z + x2.w*e2.w;
    float nsq = e1.x*e1.x + e1.y*e1.y + e1.z*e1.z + e1.w*e1.w
              + e2.x*e2.x + e2.y*e2.y + e2.z*e2.z + e2.w*e2.w;
    float xx  = x1.x*x1.x + x1.y*x1.y + x1.z*x1.z + x1.w*x1.w
              + x2.x*x2.x + x2.y*x2.y + x2.z*x2.z + x2.w*x2.w;
#pragma unroll
    for (int o = 16; o; o >>= 1) {
        dot += __shfl_xor_sync(0xffffffffu, dot, o);
        nsq += __shfl_xor_sync(0xffffffffu, nsq, o);
        xx  += __shfl_xor_sync(0xffffffffu, xx,  o);
    }

    float scalar = dot / (nsq + 1e-8f);

    float4* oq = (float4*)(xq + (size_t)b * Dsz);
    oq[lane]      = make_float4(scalar*e1.x, scalar*e1.y, scalar*e1.z, scalar*e1.w);
    oq[lane + 32] = make_float4(scalar*e2.x, scalar*e2.y, scalar*e2.z, scalar*e2.w);

    if (lane == 0) {
        float pd = scalar * dot;               // proj . x
        float pp = scalar * scalar * nsq;      // ||proj||^2
        float commit = pd / (fmaxf(sqrtf(pp), 1e-8f) * fmaxf(sqrtf(xx), 1e-8f));
        part[w] = 1.0f - commit;
        if (w_sca) out_sca[b] = scalar;
    }
    __syncthreads();
    if (threadIdx.x == 0) {
        float s = 0.0f;
#pragma unroll
        for (int i = 0; i < 8; i++) s += part[i];
        g_partial[blockIdx.x] = s;
    }
}

// ============================================================================
// Kernel D: deterministic loss reduction
// ============================================================================
__global__ void k_loss(float* __restrict__ out_loss) {
    __shared__ float red[256];
    int tid = threadIdx.x;
    float s = 0.0f;
    for (int i = tid; i < Bsz / 8; i += 256) s += g_partial[i];   // fixed order
    red[tid] = s;
    __syncthreads();
#pragma unroll
    for (int o = 128; o; o >>= 1) {
        if (tid < o) red[tid] += red[tid + o];
        __syncthreads();
    }
    if (tid == 0) out_loss[0] = 0.25f * red[0] * (1.0f / (float)Bsz);
}

// ============================================================================
// launch
// ============================================================================
extern "C" void kernel_launch(void* const* d_in, const int* in_sizes, int n_in,
                              void* d_out, int out_size) {
    const float* X = (const float*)d_in[0];   // (B, D)
    const float* E = (const float*)d_in[1];   // (N, D)
    float* out = (float*)d_out;

    const long long BD = (long long)Bsz * Dsz;
    long long osz = (long long)out_size;

    // Graded tuple flattening: write each tail section iff out_size reaches it.
    int w_loss = (osz >= BD + 1);
    int w_idx  = (osz >= BD + 1 + (long long)Bsz);
    int w_sca  = (osz >= BD + 1 + 2LL * (long long)Bsz);

    float* xq       = out;
    float* out_loss = out + BD;
    float* out_idx  = out + BD + 1;
    float* out_sca  = out + BD + 1 + Bsz;

    (void)cudaFuncSetAttribute(k_gemm_argmax,
                               cudaFuncAttributeMaxDynamicSharedMemorySize, SMEM_BYTES);

    k_rnorm<<<Nsz / 8, 256>>>(E);
    k_gemm_argmax<<<Bsz / BM, 256, SMEM_BYTES>>>(X, E, out_idx, w_idx);
    k_epilogue<<<Bsz / 8, 256>>>(X, E, xq, out_sca, w_sca);
    if (w_loss) k_loss<<<1, 256>>>(out_loss);
}

// round 10
// speedup vs baseline: 1.4954x; 1.4954x over previous
#include <cuda_runtime.h>
#include <cuda_bf16.h>
#include <math_constants.h>
#include <cstdint>

// ============================================================================
// CosineVectorQuantizer on GB300 — bf16x6 emulated-fp32 GEMM via mma.sync
// (harness ptxas targets sm_103 WITHOUT the 'a' feature: no tcgen05/TMEM.
//  mma.sync.m16n8k16 bf16 + ldmatrix + cp.async are all plain-sm_103 legal.)
//
//   x: (32768, 256) fp32    embedding: (8192, 256) fp32
//   out (fp32 flat): x_q (B*D) | loss (1) | indices (B) | scalar (B)
//
// score(b,n) = (x_b . e_n) * rnorm_n computed exactly to fp32 class:
//   x = x1+x2+x3 (exact bf16 3-split), e likewise;
//   dot = x1e1+x1e2+x2e1+x2e2+x1e3+x3e1  (dropped terms <= 2^-26)
// => one bf16 GEMM, K' = 6*256 = 1536, fp32 register accumulation.
// ============================================================================

#define Bsz 32768
#define Dsz 256
#define Nsz 8192

#define NB 256                  // codes per chunk
#define NCH (Nsz / NB)          // 32
#define NSTAGE 24               // 6 term-pairs * 4 k-stages of 64 bf16

// term tables (nibble-packed): products (1,1)(1,2)(2,1)(2,2)(1,3)(3,1), 0-based
#define TA_PACK 0x201100u
#define TB_PACK 0x021010u

// ---- GEMM smem layout (bytes) ----
#define A_BUF   16384           // 128 rows x 64 bf16 (swizzled image)
#define B_OFF   32768
#define B_BUF   32768           // 256 rows x 64 bf16
#define RNS_OFF 98304           // 256 floats
#define RED_OFF 99328           // 128 x 4 float2
#define SMEM_G  103424

// -------- device scratch (static globals: the sanctioned no-alloc path) -----
__device__ uint4 X3u[(size_t)12 * 32768 * 8];   // [term*4+ks][row][8 uint4]
__device__ uint4 E3u[(size_t)12 * 8192 * 8];
__device__ float g_rnorm[Nsz];
__device__ int   g_idx[Bsz];
__device__ float g_partial[Bsz / 8];

// ---------------------------------------------------------------------------
__device__ __forceinline__ uint32_t smem_to_u32(const void* p) {
    uint32_t a;
    asm("{ .reg .u64 t; cvta.to.shared.u64 t, %1; cvt.u32.u64 %0, t; }"
        : "=r"(a) : "l"(p));
    return a;
}
__device__ __forceinline__ void cp16(uint32_t s, const void* g) {
    asm volatile("cp.async.cg.shared.global [%0], [%1], 16;" :: "r"(s), "l"(g));
}
#define CP_COMMIT() asm volatile("cp.async.commit_group;" ::: "memory")
#define CP_WAIT0()  asm volatile("cp.async.wait_group 0;" ::: "memory")

__device__ __forceinline__ void ldsm4(uint32_t* r, uint32_t addr) {
    asm volatile("ldmatrix.sync.aligned.m8n8.x4.shared.b16 {%0,%1,%2,%3}, [%4];"
                 : "=r"(r[0]), "=r"(r[1]), "=r"(r[2]), "=r"(r[3]) : "r"(addr));
}
__device__ __forceinline__ void mma16816(float* d, const uint32_t* a,
                                         uint32_t b0, uint32_t b1) {
    asm volatile("mma.sync.aligned.m16n8k16.row.col.f32.bf16.bf16.f32 "
                 "{%0,%1,%2,%3}, {%4,%5,%6,%7}, {%8,%9}, {%0,%1,%2,%3};"
                 : "+f"(d[0]), "+f"(d[1]), "+f"(d[2]), "+f"(d[3])
                 : "r"(a[0]), "r"(a[1]), "r"(a[2]), "r"(a[3]), "r"(b0), "r"(b1));
}

// ============================================================================
// Kernel A: codebook inverse norms
// ============================================================================
__global__ void k_rnorm(const float* __restrict__ E) {
    int wid = threadIdx.x >> 5, lane = threadIdx.x & 31;
    int n = blockIdx.x * 8 + wid;
    const float4* e = (const float4*)(E + (size_t)n * Dsz);
    float4 v1 = e[lane], v2 = e[lane + 32];
    float ss = v1.x*v1.x + v1.y*v1.y + v1.z*v1.z + v1.w*v1.w
             + v2.x*v2.x + v2.y*v2.y + v2.z*v2.z + v2.w*v2.w;
#pragma unroll
    for (int o = 16; o; o >>= 1) ss += __shfl_xor_sync(0xffffffffu, ss, o);
    if (lane == 0) g_rnorm[n] = 1.0f / fmaxf(sqrtf(ss), 1e-12f);
}

// ============================================================================
// Kernel B: exact bf16 3-split, stored swizzled: (r, 16B-group g) at g^(r&7)
// ============================================================================
__device__ __forceinline__ uint32_t pack_bf2(unsigned short lo, unsigned short hi) {
    return (uint32_t)lo | ((uint32_t)hi << 16);
}
__global__ void k_convert(const float* __restrict__ S, uint4* __restrict__ D, int rows) {
    int gt = blockIdx.x * 256 + threadIdx.x;
    int r = gt >> 3, a = gt & 7;
    int sw = a ^ (r & 7);
#pragma unroll
    for (int ks = 0; ks < 4; ks++) {
        const float4* sp = (const float4*)(S + (size_t)r * Dsz + ks * 64 + a * 8);
        float4 f0 = sp[0], f1 = sp[1];
        float v[8] = {f0.x, f0.y, f0.z, f0.w, f1.x, f1.y, f1.z, f1.w};
        unsigned short t1[8], t2[8], t3[8];
#pragma unroll
        for (int e = 0; e < 8; e++) {
            __nv_bfloat16 b1 = __float2bfloat16(v[e]);
            float r1 = v[e] - __bfloat162float(b1);
            __nv_bfloat16 b2 = __float2bfloat16(r1);
            float r2 = r1 - __bfloat162float(b2);
            __nv_bfloat16 b3 = __float2bfloat16(r2);
            t1[e] = __bfloat16_as_ushort(b1);
            t2[e] = __bfloat16_as_ushort(b2);
            t3[e] = __bfloat16_as_ushort(b3);
        }
        size_t o1 = ((size_t)(0 * 4 + ks) * rows + r) * 8 + sw;
        size_t o2 = ((size_t)(1 * 4 + ks) * rows + r) * 8 + sw;
        size_t o3 = ((size_t)(2 * 4 + ks) * rows + r) * 8 + sw;
        D[o1] = make_uint4(pack_bf2(t1[0],t1[1]), pack_bf2(t1[2],t1[3]),
                           pack_bf2(t1[4],t1[5]), pack_bf2(t1[6],t1[7]));
        D[o2] = make_uint4(pack_bf2(t2[0],t2[1]), pack_bf2(t2[2],t2[3]),
                           pack_bf2(t2[4],t2[5]), pack_bf2(t2[6],t2[7]));
        D[o3] = make_uint4(pack_bf2(t3[0],t3[1]), pack_bf2(t3[2],t3[3]),
                           pack_bf2(t3[4],t3[5]), pack_bf2(t3[6],t3[7]));
    }
}

// ============================================================================
// Kernel C: bf16x6 GEMM via mma.sync + fused per-row argmax
//   CTA: 128 rows (M), 32 chunks of 256 codes, 24 stages of K=64 each.
//   Warp grid 2x4 (wm, wn): per-warp tile 64x64, acc[4][8][4] fp32.
// ============================================================================
__global__ void __launch_bounds__(256, 1)
k_gemm_mma(float* __restrict__ out_idx, int w_idx) {
    extern __shared__ char smem[];
    uint32_t sb = smem_to_u32(smem);
    float*  rns = (float*)(smem + RNS_OFF);
    float2* red = (float2*)(smem + RED_OFF);

    int tid  = threadIdx.x;
    int wid  = tid >> 5, lane = tid & 31;
    int wm   = wid >> 2, wn = wid & 3;            // 2 x 4 warp grid
    int m0   = blockIdx.x * 128;

    // ldmatrix lane roles (sub = lane>>3)
    int sub = lane >> 3;
    int la  = (sub & 1) * 8 + (lane & 7);         // A: row-in-tile, ka = k-half
    int ka  = sub >> 1;
    int lb  = (sub >> 1) * 8 + (lane & 7);        // B: row-in-tile, kb = k-half
    int kb  = sub & 1;

    float bestS = -CUDART_INF_F;                  // thread t<128 owns row t
    int   bestI = 0;

#pragma unroll 1
    for (int chunk = 0; chunk < NCH; chunk++) {
        int n0 = chunk * NB;
        rns[tid] = g_rnorm[n0 + tid];

        float acc[4][8][4];
#pragma unroll
        for (int mi = 0; mi < 4; mi++)
#pragma unroll
            for (int ni = 0; ni < 8; ni++)
#pragma unroll
                for (int q = 0; q < 4; q++) acc[mi][ni][q] = 0.0f;

        // ---- stage issue lambda-ish (macro via code dup) ----
        // prologue: stage 0 -> buf 0
        {
            int g = 0, ks = 0;
            int ta = (TA_PACK >> (4 * g)) & 15, tb = (TB_PACK >> (4 * g)) & 15;
            const uint4* As = &X3u[((size_t)(ta * 4 + ks) * Bsz + m0) * 8];
            const uint4* Bs = &E3u[((size_t)(tb * 4 + ks) * Nsz + n0) * 8];
#pragma unroll
            for (int i = 0; i < 4; i++) cp16(sb + (tid + i * 256) * 16, As + tid + i * 256);
#pragma unroll
            for (int i = 0; i < 8; i++) cp16(sb + B_OFF + (tid + i * 256) * 16, Bs + tid + i * 256);
            CP_COMMIT();
        }

        int buf = 0;
#pragma unroll 1
        for (int s = 0; s < NSTAGE; s++) {
            CP_WAIT0();
            __syncthreads();
            if (s + 1 < NSTAGE) {
                int sn = s + 1;
                int g = sn >> 2, ks = sn & 3;
                int ta = (TA_PACK >> (4 * g)) & 15, tb = (TB_PACK >> (4 * g)) & 15;
                const uint4* As = &X3u[((size_t)(ta * 4 + ks) * Bsz + m0) * 8];
                const uint4* Bs = &E3u[((size_t)(tb * 4 + ks) * Nsz + n0) * 8];
                uint32_t Ad = sb + (buf ^ 1) * A_BUF;
                uint32_t Bd = sb + B_OFF + (buf ^ 1) * B_BUF;
#pragma unroll
                for (int i = 0; i < 4; i++) cp16(Ad + (tid + i * 256) * 16, As + tid + i * 256);
#pragma unroll
                for (int i = 0; i < 8; i++) cp16(Bd + (tid + i * 256) * 16, Bs + tid + i * 256);
                CP_COMMIT();
            }

            uint32_t Ab = sb + buf * A_BUF;
            uint32_t Bb = sb + B_OFF + buf * B_BUF;
#pragma unroll
            for (int kstep = 0; kstep < 4; kstep++) {
                uint32_t a[4][4];
#pragma unroll
                for (int mi = 0; mi < 4; mi++) {
                    int r = wm * 64 + mi * 16 + la;
                    ldsm4(a[mi], Ab + r * 128 + (((kstep * 2 + ka) ^ (la & 7)) << 4));
                }
                uint32_t bq[4][4];
#pragma unroll
                for (int nj = 0; nj < 4; nj++) {
                    int r = wn * 64 + nj * 16 + lb;
                    ldsm4(bq[nj], Bb + r * 128 + (((kstep * 2 + kb) ^ (lb & 7)) << 4));
                }
#pragma unroll
                for (int mi = 0; mi < 4; mi++)
#pragma unroll
                    for (int nj = 0; nj < 4; nj++) {
                        mma16816(acc[mi][2 * nj],     a[mi], bq[nj][0], bq[nj][1]);
                        mma16816(acc[mi][2 * nj + 1], a[mi], bq[nj][2], bq[nj][3]);
                    }
            }
            __syncthreads();
            buf ^= 1;
        }

        // ---- fused argmax over this chunk ----
        // thread-local rns for its 16 columns
        float rv[8][2];
#pragma unroll
        for (int ni = 0; ni < 8; ni++)
#pragma unroll
            for (int q = 0; q < 2; q++)
                rv[ni][q] = rns[wn * 64 + ni * 8 + (lane & 3) * 2 + q];

#pragma unroll
        for (int mi = 0; mi < 4; mi++)
#pragma unroll
            for (int h = 0; h < 2; h++) {
                float s = -CUDART_INF_F;
                int   c = 0;
#pragma unroll
                for (int ni = 0; ni < 8; ni++)
#pragma unroll
                    for (int q = 0; q < 2; q++) {
                        float sc = acc[mi][ni][h * 2 + q] * rv[ni][q];
                        int col = ni * 8 + (lane & 3) * 2 + q;
                        if (sc > s || (sc == s && col < c)) { s = sc; c = col; }
                    }
                // reduce across the 4 lanes sharing this row
#pragma unroll
                for (int o = 1; o <= 2; o <<= 1) {
                    float s2 = __shfl_xor_sync(0xffffffffu, s, o);
                    int   c2 = __shfl_xor_sync(0xffffffffu, c, o);
                    if (s2 > s || (s2 == s && c2 < c)) { s = s2; c = c2; }
                }
                if ((lane & 3) == 0) {
                    int row = wm * 64 + mi * 16 + (lane >> 2) + h * 8;
                    red[row * 4 + wn] = make_float2(s, (float)(wn * 64 + c));
                }
            }
        __syncthreads();
        if (tid < 128) {
#pragma unroll
            for (int w = 0; w < 4; w++) {
                float2 e = red[tid * 4 + w];
                int gn = n0 + (int)e.y;
                if (e.x > bestS || (e.x == bestS && gn < bestI)) { bestS = e.x; bestI = gn; }
            }
        }
        __syncthreads();          // red/rns reusable next chunk
    }

    if (tid < 128) {
        int b = m0 + tid;
        g_idx[b] = bestI;
        if (w_idx) out_idx[b] = (float)bestI;
    }
}

// ============================================================================
// Kernel D: per-row projection epilogue (warp per row)
// ============================================================================
__global__ void k_epilogue(const float* __restrict__ X, const float* __restrict__ E,
                           float* __restrict__ xq, float* __restrict__ out_sca, int w_sca) {
    __shared__ float part[8];
    int w = threadIdx.x >> 5, lane = threadIdx.x & 31;
    int b = blockIdx.x * 8 + w;
    int idx = g_idx[b];

    const float4* xv = (const float4*)(X + (size_t)b   * Dsz);
    const float4* ev = (const float4*)(E + (size_t)idx * Dsz);
    float4 x1 = xv[lane], x2 = xv[lane + 32];
    float4 e1 = ev[lane], e2 = ev[lane + 32];

    float dot = x1.x*e1.x + x1.y*e1.y + x1.z*e1.z + x1.w*e1.w
              + x2.x*e2.x + x2.y*e2.y + x2.z*e2.z + x2.w*e2.w;
    float nsq = e1.x*e1.x + e1.y*e1.y + e1.z*e1.z + e1.w*e1.w
              + e2.x*e2.x + e2.y*e2.y + e2.z*e2.z + e2.w*e2.w;
    float xx  = x1.x*x1.x + x1.y*x1.y + x1.z*x1.z + x1.w*x1.w
              + x2.x*x2.x + x2.y*x2.y + x2.z*x2.z + x2.w*x2.w;
#pragma unroll
    for (int o = 16; o; o >>= 1) {
        dot += __shfl_xor_sync(0xffffffffu, dot, o);
        nsq += __shfl_xor_sync(0xffffffffu, nsq, o);
        xx  += __shfl_xor_sync(0xffffffffu, xx,  o);
    }

    float scalar = dot / (nsq + 1e-8f);

    float4* oq = (float4*)(xq + (size_t)b * Dsz);
    oq[lane]      = make_float4(scalar*e1.x, scalar*e1.y, scalar*e1.z, scalar*e1.w);
    oq[lane + 32] = make_float4(scalar*e2.x, scalar*e2.y, scalar*e2.z, scalar*e2.w);

    if (lane == 0) {
        float pd = scalar * dot;
        float pp = scalar * scalar * nsq;
        float commit = pd / (fmaxf(sqrtf(pp), 1e-8f) * fmaxf(sqrtf(xx), 1e-8f));
        part[w] = 1.0f - commit;
        if (w_sca) out_sca[b] = scalar;
    }
    __syncthreads();
    if (threadIdx.x == 0) {
        float s = 0.0f;
#pragma unroll
        for (int i = 0; i < 8; i++) s += part[i];
        g_partial[blockIdx.x] = s;
    }
}

// ============================================================================
// Kernel E: deterministic loss reduction
// ============================================================================
__global__ void k_loss(float* __restrict__ out_loss) {
    __shared__ float red[256];
    int tid = threadIdx.x;
    float s = 0.0f;
    for (int i = tid; i < Bsz / 8; i += 256) s += g_partial[i];
    red[tid] = s;
    __syncthreads();
#pragma unroll
    for (int o = 128; o; o >>= 1) {
        if (tid < o) red[tid] += red[tid + o];
        __syncthreads();
    }
    if (tid == 0) out_loss[0] = 0.25f * red[0] * (1.0f / (float)Bsz);
}

// ============================================================================
// launch
// ============================================================================
extern "C" void kernel_launch(void* const* d_in, const int* in_sizes, int n_in,
                              void* d_out, int out_size) {
    const float* X = (const float*)d_in[0];
    const float* E = (const float*)d_in[1];
    float* out = (float*)d_out;

    const long long BD = (long long)Bsz * Dsz;
    long long osz = (long long)out_size;
    int w_loss = (osz >= BD + 1);
    int w_idx  = (osz >= BD + 1 + (long long)Bsz);
    int w_sca  = (osz >= BD + 1 + 2LL * (long long)Bsz);

    float* xq       = out;
    float* out_loss = out + BD;
    float* out_idx  = out + BD + 1;
    float* out_sca  = out + BD + 1 + Bsz;

    uint4* x3; uint4* e3;
    (void)cudaGetSymbolAddress((void**)&x3, X3u);
    (void)cudaGetSymbolAddress((void**)&e3, E3u);
    (void)cudaFuncSetAttribute(k_gemm_mma,
                               cudaFuncAttributeMaxDynamicSharedMemorySize, SMEM_G);

    k_rnorm<<<Nsz / 8, 256>>>(E);
    k_convert<<<(Bsz * 8) / 256, 256>>>(X, x3, Bsz);
    k_convert<<<(Nsz * 8) / 256, 256>>>(E, e3, Nsz);
    k_gemm_mma<<<Bsz / 128, 256, SMEM_G>>>(out_idx, w_idx);
    k_epilogue<<<Bsz / 8, 256>>>(X, E, xq, out_sca, w_sca);
    if (w_loss) k_loss<<<1, 256>>>(out_loss);
}

// round 16
// speedup vs baseline: 1.5310x; 1.0238x over previous
#include <cuda_runtime.h>
#include <cuda_bf16.h>
#include <math_constants.h>
#include <cstdint>

// ============================================================================
// CosineVectorQuantizer on GB300 — bf16x6 emulated-fp32 GEMM via mma.sync
// (harness ptxas targets plain sm_103: no tcgen05/TMEM; mma.sync + ldmatrix +
//  cp.async are legal.)
//
//   x: (32768, 256) fp32    embedding: (8192, 256) fp32
//   out (fp32 flat): x_q (B*D) | loss (1) | indices (B) | scalar (B)
//
// score(b,n) = (x_b . e_n) * rnorm_n, fp32-exact via bf16 3-splits:
//   dot = x1e1+x1e2+x2e1+x2e2+x1e3+x3e1   (dropped terms <= 2^-26)
// => one bf16 GEMM, K' = 6*256 = 1536, fp32 register accumulation.
//
// GEMM: 512 thr (4x4 warps, 32x64/warp), 3-deep cp.async ring, distance-2
// prefetch, wait_group 1, ONE barrier/stage, pipeline continuous across the
// 32 N-chunks (768 flat stages).
// [R16 fix] A-tile prefetch issues exactly 1024 cp16s (i<2 @512thr); the
// previous i<4 overran A_BUF into the B slot (races inside one cp group).
// ============================================================================

#define Bsz 32768
#define Dsz 256
#define Nsz 8192

#define NB 256                  // codes per chunk
#define NCH (Nsz / NB)          // 32
#define NSTAGE 24               // 6 term-pairs * 4 k-stages of 64 bf16
#define NT (NCH * NSTAGE)       // 768 flat stages

// term tables (nibble-packed): products (1,1)(1,2)(2,1)(2,2)(1,3)(3,1), 0-based
#define TA_PACK 0x201100u
#define TB_PACK 0x021010u

// ---- GEMM smem layout (bytes) ----
#define A_BUF   16384           // 128 rows x 64 bf16 (swizzled image)
#define BUFB    49152           // A (16KB) + B (32KB) per ring slot
#define RNS_OFF 147456          // 3*BUFB
#define RED_OFF 148480          // 128 x 4 float2 (4KB)
#define SMEM_G  152576

// -------- device scratch (static globals: the sanctioned no-alloc path) -----
__device__ uint4 X3u[(size_t)12 * 32768 * 8];   // [term*4+ks][row][8 uint4]
__device__ uint4 E3u[(size_t)12 * 8192 * 8];
__device__ float g_rnorm[Nsz];
__device__ int   g_idx[Bsz];
__device__ float g_partial[Bsz / 8];

// ---------------------------------------------------------------------------
__device__ __forceinline__ uint32_t smem_to_u32(const void* p) {
    uint32_t a;
    asm("{ .reg .u64 t; cvta.to.shared.u64 t, %1; cvt.u32.u64 %0, t; }"
        : "=r"(a) : "l"(p));
    return a;
}
__device__ __forceinline__ void cp16(uint32_t s, const void* g) {
    asm volatile("cp.async.cg.shared.global [%0], [%1], 16;" :: "r"(s), "l"(g));
}
#define CP_COMMIT() asm volatile("cp.async.commit_group;" ::: "memory")
#define CP_WAIT1()  asm volatile("cp.async.wait_group 1;" ::: "memory")

__device__ __forceinline__ void ldsm4(uint32_t* r, uint32_t addr) {
    asm volatile("ldmatrix.sync.aligned.m8n8.x4.shared.b16 {%0,%1,%2,%3}, [%4];"
                 : "=r"(r[0]), "=r"(r[1]), "=r"(r[2]), "=r"(r[3]) : "r"(addr));
}
__device__ __forceinline__ void mma16816(float* d, const uint32_t* a,
                                         uint32_t b0, uint32_t b1) {
    asm volatile("mma.sync.aligned.m16n8k16.row.col.f32.bf16.bf16.f32 "
                 "{%0,%1,%2,%3}, {%4,%5,%6,%7}, {%8,%9}, {%0,%1,%2,%3};"
                 : "+f"(d[0]), "+f"(d[1]), "+f"(d[2]), "+f"(d[3])
                 : "r"(a[0]), "r"(a[1]), "r"(a[2]), "r"(a[3]), "r"(b0), "r"(b1));
}

// ============================================================================
// Kernel A: codebook inverse norms
// ============================================================================
__global__ void k_rnorm(const float* __restrict__ E) {
    int wid = threadIdx.x >> 5, lane = threadIdx.x & 31;
    int n = blockIdx.x * 8 + wid;
    const float4* e = (const float4*)(E + (size_t)n * Dsz);
    float4 v1 = e[lane], v2 = e[lane + 32];
    float ss = v1.x*v1.x + v1.y*v1.y + v1.z*v1.z + v1.w*v1.w
             + v2.x*v2.x + v2.y*v2.y + v2.z*v2.z + v2.w*v2.w;
#pragma unroll
    for (int o = 16; o; o >>= 1) ss += __shfl_xor_sync(0xffffffffu, ss, o);
    if (lane == 0) g_rnorm[n] = 1.0f / fmaxf(sqrtf(ss), 1e-12f);
}

// ============================================================================
// Kernel B: exact bf16 3-split, stored swizzled: (r, 16B-group g) at g^(r&7)
// ============================================================================
__device__ __forceinline__ uint32_t pack_bf2(unsigned short lo, unsigned short hi) {
    return (uint32_t)lo | ((uint32_t)hi << 16);
}
__global__ void k_convert(const float* __restrict__ S, uint4* __restrict__ D, int rows) {
    int gt = blockIdx.x * 256 + threadIdx.x;
    int r = gt >> 3, a = gt & 7;
    int sw = a ^ (r & 7);
#pragma unroll
    for (int ks = 0; ks < 4; ks++) {
        const float4* sp = (const float4*)(S + (size_t)r * Dsz + ks * 64 + a * 8);
        float4 f0 = sp[0], f1 = sp[1];
        float v[8] = {f0.x, f0.y, f0.z, f0.w, f1.x, f1.y, f1.z, f1.w};
        unsigned short t1[8], t2[8], t3[8];
#pragma unroll
        for (int e = 0; e < 8; e++) {
            __nv_bfloat16 b1 = __float2bfloat16(v[e]);
            float r1 = v[e] - __bfloat162float(b1);
            __nv_bfloat16 b2 = __float2bfloat16(r1);
            float r2 = r1 - __bfloat162float(b2);
            __nv_bfloat16 b3 = __float2bfloat16(r2);
            t1[e] = __bfloat16_as_ushort(b1);
            t2[e] = __bfloat16_as_ushort(b2);
            t3[e] = __bfloat16_as_ushort(b3);
        }
        size_t o1 = ((size_t)(0 * 4 + ks) * rows + r) * 8 + sw;
        size_t o2 = ((size_t)(1 * 4 + ks) * rows + r) * 8 + sw;
        size_t o3 = ((size_t)(2 * 4 + ks) * rows + r) * 8 + sw;
        D[o1] = make_uint4(pack_bf2(t1[0],t1[1]), pack_bf2(t1[2],t1[3]),
                           pack_bf2(t1[4],t1[5]), pack_bf2(t1[6],t1[7]));
        D[o2] = make_uint4(pack_bf2(t2[0],t2[1]), pack_bf2(t2[2],t2[3]),
                           pack_bf2(t2[4],t2[5]), pack_bf2(t2[6],t2[7]));
        D[o3] = make_uint4(pack_bf2(t3[0],t3[1]), pack_bf2(t3[2],t3[3]),
                           pack_bf2(t3[4],t3[5]), pack_bf2(t3[6],t3[7]));
    }
}

// ============================================================================
// Kernel C: bf16x6 GEMM via mma.sync + fused per-row argmax
//   512 thr, warp grid 4x4 (wm, wn), per-warp 32x64, acc[2][8][4].
//   3-slot cp.async ring, prefetch distance 2, continuous across chunks.
// ============================================================================
__device__ __forceinline__ void prefetch_stage(uint32_t sb, int P, int m0, int tid) {
    if (P >= NT) return;
    int chunk = P / NSTAGE;
    int s = P - chunk * NSTAGE;
    int g = s >> 2, ks = s & 3;
    int ta = (TA_PACK >> (4 * g)) & 15, tb = (TB_PACK >> (4 * g)) & 15;
    int n0 = chunk * NB;
    const uint4* As = &X3u[((size_t)(ta * 4 + ks) * Bsz + m0) * 8];
    const uint4* Bs = &E3u[((size_t)(tb * 4 + ks) * Nsz + n0) * 8];
    uint32_t Ab = sb + (P % 3) * BUFB;
    uint32_t Bb = Ab + A_BUF;
#pragma unroll
    for (int i = 0; i < 2; i++) cp16(Ab + (tid + i * 512) * 16, As + tid + i * 512);  // 1024 uint4 = 16KB
#pragma unroll
    for (int i = 0; i < 4; i++) cp16(Bb + (tid + i * 512) * 16, Bs + tid + i * 512);  // 2048 uint4 = 32KB
}

__global__ void __launch_bounds__(512, 1)
k_gemm_mma(float* __restrict__ out_idx, int w_idx) {
    extern __shared__ char smem[];
    uint32_t sb = smem_to_u32(smem);
    float*  rns = (float*)(smem + RNS_OFF);
    float2* red = (float2*)(smem + RED_OFF);

    int tid  = threadIdx.x;
    int wid  = tid >> 5, lane = tid & 31;
    int wm   = wid >> 2, wn = wid & 3;            // 4 x 4 warp grid
    int m0   = blockIdx.x * 128;

    // ldmatrix lane roles (sub = lane>>3)
    int sub = lane >> 3;
    int la  = (sub & 1) * 8 + (lane & 7);         // A: row-in-tile; ka = k-half
    int ka  = sub >> 1;
    int lb  = (sub >> 1) * 8 + (lane & 7);        // B: row-in-tile; kb = k-half
    int kb  = sub & 1;

    float bestS = -CUDART_INF_F;                  // thread t<128 owns row t
    int   bestI = 0;

    // pipeline prologue: flat stages 0, 1
    prefetch_stage(sb, 0, m0, tid); CP_COMMIT();
    prefetch_stage(sb, 1, m0, tid); CP_COMMIT();

#pragma unroll 1
    for (int chunk = 0; chunk < NCH; chunk++) {
        int n0 = chunk * NB;

        float acc[2][8][4];
#pragma unroll
        for (int mi = 0; mi < 2; mi++)
#pragma unroll
            for (int ni = 0; ni < 8; ni++)
#pragma unroll
                for (int q = 0; q < 4; q++) acc[mi][ni][q] = 0.0f;

#pragma unroll 1
        for (int s = 0; s < NSTAGE; s++) {
            int F = chunk * NSTAGE + s;
            CP_WAIT1();                 // group F complete (F+1 may stay in flight)
            __syncthreads();            // F's data visible; nobody still on F-1's buffer
            if (s == 0 && tid < NB) rns[tid] = g_rnorm[n0 + tid];
            prefetch_stage(sb, F + 2, m0, tid);   // overwrites slot retired at F-1
            CP_COMMIT();                          // (empty group when F+2 >= NT)

            uint32_t Ab = sb + (F % 3) * BUFB;
            uint32_t Bb = Ab + A_BUF;
#pragma unroll
            for (int kstep = 0; kstep < 4; kstep++) {
                uint32_t a[2][4];
#pragma unroll
                for (int mi = 0; mi < 2; mi++) {
                    int r = wm * 32 + mi * 16 + la;
                    ldsm4(a[mi], Ab + r * 128 + (((kstep * 2 + ka) ^ (la & 7)) << 4));
                }
                uint32_t bq[4][4];
#pragma unroll
                for (int nj = 0; nj < 4; nj++) {
                    int r = wn * 64 + nj * 16 + lb;
                    ldsm4(bq[nj], Bb + r * 128 + (((kstep * 2 + kb) ^ (lb & 7)) << 4));
                }
#pragma unroll
                for (int mi = 0; mi < 2; mi++)
#pragma unroll
                    for (int nj = 0; nj < 4; nj++) {
                        mma16816(acc[mi][2 * nj],     a[mi], bq[nj][0], bq[nj][1]);
                        mma16816(acc[mi][2 * nj + 1], a[mi], bq[nj][2], bq[nj][3]);
                    }
            }
        }

        // ---- fused argmax over this chunk (rns visible via stage barriers) ----
        float rv[8][2];
#pragma unroll
        for (int ni = 0; ni < 8; ni++)
#pragma unroll
            for (int q = 0; q < 2; q++)
                rv[ni][q] = rns[wn * 64 + ni * 8 + (lane & 3) * 2 + q];

#pragma unroll
        for (int mi = 0; mi < 2; mi++)
#pragma unroll
            for (int h = 0; h < 2; h++) {
                float s = -CUDART_INF_F;
                int   c = 0;
#pragma unroll
                for (int ni = 0; ni < 8; ni++)
#pragma unroll
                    for (int q = 0; q < 2; q++) {
                        float sc = acc[mi][ni][h * 2 + q] * rv[ni][q];
                        int col = ni * 8 + (lane & 3) * 2 + q;
                        if (sc > s || (sc == s && col < c)) { s = sc; c = col; }
                    }
#pragma unroll
                for (int o = 1; o <= 2; o <<= 1) {
                    float s2 = __shfl_xor_sync(0xffffffffu, s, o);
                    int   c2 = __shfl_xor_sync(0xffffffffu, c, o);
                    if (s2 > s || (s2 == s && c2 < c)) { s = s2; c = c2; }
                }
                if ((lane & 3) == 0) {
                    int row = wm * 32 + mi * 16 + (lane >> 2) + h * 8;
                    red[row * 4 + wn] = make_float2(s, (float)(wn * 64 + c));
                }
            }
        __syncthreads();
        if (tid < 128) {
#pragma unroll
            for (int w = 0; w < 4; w++) {
                float2 e = red[tid * 4 + w];
                int gn = n0 + (int)e.y;
                if (e.x > bestS || (e.x == bestS && gn < bestI)) { bestS = e.x; bestI = gn; }
            }
        }
        // next chunk's stage-0 wait+barrier orders red/rns reuse
    }

    if (tid < 128) {
        int b = m0 + tid;
        g_idx[b] = bestI;
        if (w_idx) out_idx[b] = (float)bestI;
    }
}

// ============================================================================
// Kernel D: per-row projection epilogue (warp per row)
// ============================================================================
__global__ void k_epilogue(const float* __restrict__ X, const float* __restrict__ E,
                           float* __restrict__ xq, float* __restrict__ out_sca, int w_sca) {
    __shared__ float part[8];
    int w = threadIdx.x >> 5, lane = threadIdx.x & 31;
    int b = blockIdx.x * 8 + w;
    int idx = g_idx[b];

    const float4* xv = (const float4*)(X + (size_t)b   * Dsz);
    const float4* ev = (const float4*)(E + (size_t)idx * Dsz);
    float4 x1 = xv[lane], x2 = xv[lane + 32];
    float4 e1 = ev[lane], e2 = ev[lane + 32];

    float dot = x1.x*e1.x + x1.y*e1.y + x1.z*e1.z + x1.w*e1.w
              + x2.x*e2.x + x2.y*e2.y + x2.z*e2.z + x2.w*e2.w;
    float nsq = e1.x*e1.x + e1.y*e1.y + e1.z*e1.z + e1.w*e1.w
              + e2.x*e2.x + e2.y*e2.y + e2.z*e2.z + e2.w*e2.w;
    float xx  = x1.x*x1.x + x1.y*x1.y + x1.z*x1.z + x1.w*x1.w
              + x2.x*x2.x + x2.y*x2.y + x2.z*x2.z + x2.w*x2.w;
#pragma unroll
    for (int o = 16; o; o >>= 1) {
        dot += __shfl_xor_sync(0xffffffffu, dot, o);
        nsq += __shfl_xor_sync(0xffffffffu, nsq, o);
        xx  += __shfl_xor_sync(0xffffffffu, xx,  o);
    }

    float scalar = dot / (nsq + 1e-8f);

    float4* oq = (float4*)(xq + (size_t)b * Dsz);
    oq[lane]      = make_float4(scalar*e1.x, scalar*e1.y, scalar*e1.z, scalar*e1.w);
    oq[lane + 32] = make_float4(scalar*e2.x, scalar*e2.y, scalar*e2.z, scalar*e2.w);

    if (lane == 0) {
        float pd = scalar * dot;
        float pp = scalar * scalar * nsq;
        float commit = pd / (fmaxf(sqrtf(pp), 1e-8f) * fmaxf(sqrtf(xx), 1e-8f));
        part[w] = 1.0f - commit;
        if (w_sca) out_sca[b] = scalar;
    }
    __syncthreads();
    if (threadIdx.x == 0) {
        float s = 0.0f;
#pragma unroll
        for (int i = 0; i < 8; i++) s += part[i];
        g_partial[blockIdx.x] = s;
    }
}

// ============================================================================
// Kernel E: deterministic loss reduction
// ============================================================================
__global__ void k_loss(float* __restrict__ out_loss) {
    __shared__ float red[256];
    int tid = threadIdx.x;
    float s = 0.0f;
    for (int i = tid; i < Bsz / 8; i += 256) s += g_partial[i];
    red[tid] = s;
    __syncthreads();
#pragma unroll
    for (int o = 128; o; o >>= 1) {
        if (tid < o) red[tid] += red[tid + o];
        __syncthreads();
    }
    if (tid == 0) out_loss[0] = 0.25f * red[0] * (1.0f / (float)Bsz);
}

// ============================================================================
// launch
// ============================================================================
extern "C" void kernel_launch(void* const* d_in, const int* in_sizes, int n_in,
                              void* d_out, int out_size) {
    const float* X = (const float*)d_in[0];
    const float* E = (const float*)d_in[1];
    float* out = (float*)d_out;

    const long long BD = (long long)Bsz * Dsz;
    long long osz = (long long)out_size;
    int w_loss = (osz >= BD + 1);
    int w_idx  = (osz >= BD + 1 + (long long)Bsz);
    int w_sca  = (osz >= BD + 1 + 2LL * (long long)Bsz);

    float* xq       = out;
    float* out_loss = out + BD;
    float* out_idx  = out + BD + 1;
    float* out_sca  = out + BD + 1 + Bsz;

    uint4* x3; uint4* e3;
    (void)cudaGetSymbolAddress((void**)&x3, X3u);
    (void)cudaGetSymbolAddress((void**)&e3, E3u);
    (void)cudaFuncSetAttribute(k_gemm_mma,
                               cudaFuncAttributeMaxDynamicSharedMemorySize, SMEM_G);

    k_rnorm<<<Nsz / 8, 256>>>(E);
    k_convert<<<(Bsz * 8) / 256, 256>>>(X, x3, Bsz);
    k_convert<<<(Nsz * 8) / 256, 256>>>(E, e3, Nsz);
    k_gemm_mma<<<Bsz / 128, 512, SMEM_G>>>(out_idx, w_idx);
    k_epilogue<<<Bsz / 8, 256>>>(X, E, xq, out_sca, w_sca);
    if (w_loss) k_loss<<<1, 256>>>(out_loss);
}

// round 17
// speedup vs baseline: 1.6492x; 1.0772x over previous
#include <cuda_runtime.h>
#include <cuda_bf16.h>
#include <math_constants.h>
#include <cstdint>

// ============================================================================
// CosineVectorQuantizer on GB300 — bf16x6 emulated-fp32 GEMM via mma.sync
// (harness ptxas targets plain sm_103: no tcgen05/TMEM; mma.sync + ldmatrix +
//  cp.async are legal.)
//
//   x: (32768, 256) fp32    embedding: (8192, 256) fp32
//   out (fp32 flat): x_q (B*D) | loss (1) | indices (B) | scalar (B)
//
// score(b,n) = (x_b . e_n) * rnorm_n, fp32-exact via bf16 3-splits:
//   dot = x1e1+x1e2+x2e1+x2e2+x1e3+x3e1   (dropped terms <= 2^-26)
// => one bf16 GEMM, K' = 6*256 = 1536, fp32 register accumulation.
//
// R17: TWO CTAs per SM for cross-CTA pipeline overlap (the 1-CTA version's
// per-stage barrier aligned all warps; tensor pipe idled 40%).
//   256 thr/CTA, warp grid 2x4, warp tile 64x32 (acc 64 regs, ~115 live),
//   CTA tile 128(M) x 128(N-chunk), 64 chunks x 24 stages, 3-slot cp.async
//   ring, distance-2 prefetch, wait_group 1, one barrier/stage.
// ============================================================================

#define Bsz 32768
#define Dsz 256
#define Nsz 8192

#define NB 128                  // codes per chunk
#define NCH (Nsz / NB)          // 64
#define NSTAGE 24               // 6 term-pairs * 4 k-stages of 64 bf16
#define NT (NCH * NSTAGE)       // 1536 flat stages

// term tables (nibble-packed): products (1,1)(1,2)(2,1)(2,2)(1,3)(3,1), 0-based
#define TA_PACK 0x201100u
#define TB_PACK 0x021010u

// ---- GEMM smem layout (bytes) ----
#define A_BUF   16384           // 128 rows x 64 bf16 (swizzled image)
#define BUFB    32768           // A (16KB) + B (16KB) per ring slot
#define RNS_OFF 98304           // 3*BUFB
#define RED_OFF 98816           // 128 x 4 float2 (4KB)
#define SMEM_G  102912

// -------- device scratch (static globals: the sanctioned no-alloc path) -----
__device__ uint4 X3u[(size_t)12 * 32768 * 8];   // [term*4+ks][row][8 uint4]
__device__ uint4 E3u[(size_t)12 * 8192 * 8];
__device__ float g_rnorm[Nsz];
__device__ int   g_idx[Bsz];
__device__ float g_partial[Bsz / 8];

// ---------------------------------------------------------------------------
__device__ __forceinline__ uint32_t smem_to_u32(const void* p) {
    uint32_t a;
    asm("{ .reg .u64 t; cvta.to.shared.u64 t, %1; cvt.u32.u64 %0, t; }"
        : "=r"(a) : "l"(p));
    return a;
}
__device__ __forceinline__ void cp16(uint32_t s, const void* g) {
    asm volatile("cp.async.cg.shared.global [%0], [%1], 16;" :: "r"(s), "l"(g));
}
#define CP_COMMIT() asm volatile("cp.async.commit_group;" ::: "memory")
#define CP_WAIT1()  asm volatile("cp.async.wait_group 1;" ::: "memory")

__device__ __forceinline__ void ldsm4(uint32_t* r, uint32_t addr) {
    asm volatile("ldmatrix.sync.aligned.m8n8.x4.shared.b16 {%0,%1,%2,%3}, [%4];"
                 : "=r"(r[0]), "=r"(r[1]), "=r"(r[2]), "=r"(r[3]) : "r"(addr));
}
__device__ __forceinline__ void mma16816(float* d, const uint32_t* a,
                                         uint32_t b0, uint32_t b1) {
    asm volatile("mma.sync.aligned.m16n8k16.row.col.f32.bf16.bf16.f32 "
                 "{%0,%1,%2,%3}, {%4,%5,%6,%7}, {%8,%9}, {%0,%1,%2,%3};"
                 : "+f"(d[0]), "+f"(d[1]), "+f"(d[2]), "+f"(d[3])
                 : "r"(a[0]), "r"(a[1]), "r"(a[2]), "r"(a[3]), "r"(b0), "r"(b1));
}

// ============================================================================
// Kernel A: codebook inverse norms
// ============================================================================
__global__ void k_rnorm(const float* __restrict__ E) {
    int wid = threadIdx.x >> 5, lane = threadIdx.x & 31;
    int n = blockIdx.x * 8 + wid;
    const float4* e = (const float4*)(E + (size_t)n * Dsz);
    float4 v1 = e[lane], v2 = e[lane + 32];
    float ss = v1.x*v1.x + v1.y*v1.y + v1.z*v1.z + v1.w*v1.w
             + v2.x*v2.x + v2.y*v2.y + v2.z*v2.z + v2.w*v2.w;
#pragma unroll
    for (int o = 16; o; o >>= 1) ss += __shfl_xor_sync(0xffffffffu, ss, o);
    if (lane == 0) g_rnorm[n] = 1.0f / fmaxf(sqrtf(ss), 1e-12f);
}

// ============================================================================
// Kernel B: exact bf16 3-split, stored swizzled: (r, 16B-group g) at g^(r&7)
// ============================================================================
__device__ __forceinline__ uint32_t pack_bf2(unsigned short lo, unsigned short hi) {
    return (uint32_t)lo | ((uint32_t)hi << 16);
}
__global__ void k_convert(const float* __restrict__ S, uint4* __restrict__ D, int rows) {
    int gt = blockIdx.x * 256 + threadIdx.x;
    int r = gt >> 3, a = gt & 7;
    int sw = a ^ (r & 7);
#pragma unroll
    for (int ks = 0; ks < 4; ks++) {
        const float4* sp = (const float4*)(S + (size_t)r * Dsz + ks * 64 + a * 8);
        float4 f0 = sp[0], f1 = sp[1];
        float v[8] = {f0.x, f0.y, f0.z, f0.w, f1.x, f1.y, f1.z, f1.w};
        unsigned short t1[8], t2[8], t3[8];
#pragma unroll
        for (int e = 0; e < 8; e++) {
            __nv_bfloat16 b1 = __float2bfloat16(v[e]);
            float r1 = v[e] - __bfloat162float(b1);
            __nv_bfloat16 b2 = __float2bfloat16(r1);
            float r2 = r1 - __bfloat162float(b2);
            __nv_bfloat16 b3 = __float2bfloat16(r2);
            t1[e] = __bfloat16_as_ushort(b1);
            t2[e] = __bfloat16_as_ushort(b2);
            t3[e] = __bfloat16_as_ushort(b3);
        }
        size_t o1 = ((size_t)(0 * 4 + ks) * rows + r) * 8 + sw;
        size_t o2 = ((size_t)(1 * 4 + ks) * rows + r) * 8 + sw;
        size_t o3 = ((size_t)(2 * 4 + ks) * rows + r) * 8 + sw;
        D[o1] = make_uint4(pack_bf2(t1[0],t1[1]), pack_bf2(t1[2],t1[3]),
                           pack_bf2(t1[4],t1[5]), pack_bf2(t1[6],t1[7]));
        D[o2] = make_uint4(pack_bf2(t2[0],t2[1]), pack_bf2(t2[2],t2[3]),
                           pack_bf2(t2[4],t2[5]), pack_bf2(t2[6],t2[7]));
        D[o3] = make_uint4(pack_bf2(t3[0],t3[1]), pack_bf2(t3[2],t3[3]),
                           pack_bf2(t3[4],t3[5]), pack_bf2(t3[6],t3[7]));
    }
}

// ============================================================================
// Kernel C: bf16x6 GEMM via mma.sync + fused per-row argmax
//   256 thr, warp grid 2x4 (wm, wn), per-warp 64x32, acc[4][4][4].
//   3-slot cp.async ring, prefetch distance 2, continuous across chunks.
//   2 CTAs/SM co-resident for cross-CTA latency hiding.
// ============================================================================
__device__ __forceinline__ void prefetch_stage(uint32_t sb, int P, int m0, int tid) {
    if (P >= NT) return;
    int chunk = P / NSTAGE;
    int s = P - chunk * NSTAGE;
    int g = s >> 2, ks = s & 3;
    int ta = (TA_PACK >> (4 * g)) & 15, tb = (TB_PACK >> (4 * g)) & 15;
    int n0 = chunk * NB;
    const uint4* As = &X3u[((size_t)(ta * 4 + ks) * Bsz + m0) * 8];
    const uint4* Bs = &E3u[((size_t)(tb * 4 + ks) * Nsz + n0) * 8];
    uint32_t Ab = sb + (P % 3) * BUFB;
    uint32_t Bb = Ab + A_BUF;
#pragma unroll
    for (int i = 0; i < 4; i++) cp16(Ab + (tid + i * 256) * 16, As + tid + i * 256);  // 1024 uint4
#pragma unroll
    for (int i = 0; i < 4; i++) cp16(Bb + (tid + i * 256) * 16, Bs + tid + i * 256);  // 1024 uint4
}

__global__ void __launch_bounds__(256, 2)
k_gemm_mma(float* __restrict__ out_idx, int w_idx) {
    extern __shared__ char smem[];
    uint32_t sb = smem_to_u32(smem);
    float*  rns = (float*)(smem + RNS_OFF);
    float2* red = (float2*)(smem + RED_OFF);

    int tid  = threadIdx.x;
    int wid  = tid >> 5, lane = tid & 31;
    int wm   = wid >> 2, wn = wid & 3;            // 2 x 4 warp grid
    int m0   = blockIdx.x * 128;

    // ldmatrix lane roles (sub = lane>>3)
    int sub = lane >> 3;
    int la  = (sub & 1) * 8 + (lane & 7);         // A: row-in-tile; ka = k-half
    int ka  = sub >> 1;
    int lb  = (sub >> 1) * 8 + (lane & 7);        // B: row-in-tile; kb = k-half
    int kb  = sub & 1;

    float bestS = -CUDART_INF_F;                  // thread t<128 owns row t
    int   bestI = 0;

    // pipeline prologue: flat stages 0, 1
    prefetch_stage(sb, 0, m0, tid); CP_COMMIT();
    prefetch_stage(sb, 1, m0, tid); CP_COMMIT();

#pragma unroll 1
    for (int chunk = 0; chunk < NCH; chunk++) {
        int n0 = chunk * NB;

        float acc[4][4][4];
#pragma unroll
        for (int mi = 0; mi < 4; mi++)
#pragma unroll
            for (int ni = 0; ni < 4; ni++)
#pragma unroll
                for (int q = 0; q < 4; q++) acc[mi][ni][q] = 0.0f;

#pragma unroll 1
        for (int s = 0; s < NSTAGE; s++) {
            int F = chunk * NSTAGE + s;
            CP_WAIT1();                 // group F complete (F+1 may stay in flight)
            __syncthreads();            // F's data visible; nobody still on F-1's buffer
            if (s == 0 && tid < NB) rns[tid] = g_rnorm[n0 + tid];
            prefetch_stage(sb, F + 2, m0, tid);   // overwrites slot retired at F-1
            CP_COMMIT();                          // (empty group when F+2 >= NT)

            uint32_t Ab = sb + (F % 3) * BUFB;
            uint32_t Bb = Ab + A_BUF;
#pragma unroll
            for (int kstep = 0; kstep < 4; kstep++) {
                uint32_t a[4][4];
#pragma unroll
                for (int mi = 0; mi < 4; mi++) {
                    int r = wm * 64 + mi * 16 + la;
                    ldsm4(a[mi], Ab + r * 128 + (((kstep * 2 + ka) ^ (la & 7)) << 4));
                }
                uint32_t bq[2][4];
#pragma unroll
                for (int nj = 0; nj < 2; nj++) {
                    int r = wn * 32 + nj * 16 + lb;
                    ldsm4(bq[nj], Bb + r * 128 + (((kstep * 2 + kb) ^ (lb & 7)) << 4));
                }
#pragma unroll
                for (int mi = 0; mi < 4; mi++)
#pragma unroll
                    for (int nj = 0; nj < 2; nj++) {
                        mma16816(acc[mi][2 * nj],     a[mi], bq[nj][0], bq[nj][1]);
                        mma16816(acc[mi][2 * nj + 1], a[mi], bq[nj][2], bq[nj][3]);
                    }
            }
        }

        // ---- fused argmax over this chunk (rns visible via stage barriers) ----
        float rv[4][2];
#pragma unroll
        for (int ni = 0; ni < 4; ni++)
#pragma unroll
            for (int q = 0; q < 2; q++)
                rv[ni][q] = rns[wn * 32 + ni * 8 + (lane & 3) * 2 + q];

#pragma unroll
        for (int mi = 0; mi < 4; mi++)
#pragma unroll
            for (int h = 0; h < 2; h++) {
                float s = -CUDART_INF_F;
                int   c = 0;
#pragma unroll
                for (int ni = 0; ni < 4; ni++)
#pragma unroll
                    for (int q = 0; q < 2; q++) {
                        float sc = acc[mi][ni][h * 2 + q] * rv[ni][q];
                        int col = ni * 8 + (lane & 3) * 2 + q;
                        if (sc > s || (sc == s && col < c)) { s = sc; c = col; }
                    }
#pragma unroll
                for (int o = 1; o <= 2; o <<= 1) {
                    float s2 = __shfl_xor_sync(0xffffffffu, s, o);
                    int   c2 = __shfl_xor_sync(0xffffffffu, c, o);
                    if (s2 > s || (s2 == s && c2 < c)) { s = s2; c = c2; }
                }
                if ((lane & 3) == 0) {
                    int row = wm * 64 + mi * 16 + (lane >> 2) + h * 8;
                    red[row * 4 + wn] = make_float2(s, (float)(wn * 32 + c));
                }
            }
        __syncthreads();
        if (tid < 128) {
#pragma unroll
            for (int w = 0; w < 4; w++) {
                float2 e = red[tid * 4 + w];
                int gn = n0 + (int)e.y;
                if (e.x > bestS || (e.x == bestS && gn < bestI)) { bestS = e.x; bestI = gn; }
            }
        }
        // next chunk's stage-0 wait+barrier orders red/rns reuse
    }

    if (tid < 128) {
        int b = m0 + tid;
        g_idx[b] = bestI;
        if (w_idx) out_idx[b] = (float)bestI;
    }
}

// ============================================================================
// Kernel D: per-row projection epilogue (warp per row)
// ============================================================================
__global__ void k_epilogue(const float* __restrict__ X, const float* __restrict__ E,
                           float* __restrict__ xq, float* __restrict__ out_sca, int w_sca) {
    __shared__ float part[8];
    int w = threadIdx.x >> 5, lane = threadIdx.x & 31;
    int b = blockIdx.x * 8 + w;
    int idx = g_idx[b];

    const float4* xv = (const float4*)(X + (size_t)b   * Dsz);
    const float4* ev = (const float4*)(E + (size_t)idx * Dsz);
    float4 x1 = xv[lane], x2 = xv[lane + 32];
    float4 e1 = ev[lane], e2 = ev[lane + 32];

    float dot = x1.x*e1.x + x1.y*e1.y + x1.z*e1.z + x1.w*e1.w
              + x2.x*e2.x + x2.y*e2.y + x2.z*e2.z + x2.w*e2.w;
    float nsq = e1.x*e1.x + e1.y*e1.y + e1.z*e1.z + e1.w*e1.w
              + e2.x*e2.x + e2.y*e2.y + e2.z*e2.z + e2.w*e2.w;
    float xx  = x1.x*x1.x + x1.y*x1.y + x1.z*x1.z + x1.w*x1.w
              + x2.x*x2.x + x2.y*x2.y + x2.z*x2.z + x2.w*x2.w;
#pragma unroll
    for (int o = 16; o; o >>= 1) {
        dot += __shfl_xor_sync(0xffffffffu, dot, o);
        nsq += __shfl_xor_sync(0xffffffffu, nsq, o);
        xx  += __shfl_xor_sync(0xffffffffu, xx,  o);
    }

    float scalar = dot / (nsq + 1e-8f);

    float4* oq = (float4*)(xq + (size_t)b * Dsz);
    oq[lane]      = make_float4(scalar*e1.x, scalar*e1.y, scalar*e1.z, scalar*e1.w);
    oq[lane + 32] = make_float4(scalar*e2.x, scalar*e2.y, scalar*e2.z, scalar*e2.w);

    if (lane == 0) {
        float pd = scalar * dot;
        float pp = scalar * scalar * nsq;
        float commit = pd / (fmaxf(sqrtf(pp), 1e-8f) * fmaxf(sqrtf(xx), 1e-8f));
        part[w] = 1.0f - commit;
        if (w_sca) out_sca[b] = scalar;
    }
    __syncthreads();
    if (threadIdx.x == 0) {
        float s = 0.0f;
#pragma unroll
        for (int i = 0; i < 8; i++) s += part[i];
        g_partial[blockIdx.x] = s;
    }
}

// ============================================================================
// Kernel E: deterministic loss reduction
// ============================================================================
__global__ void k_loss(float* __restrict__ out_loss) {
    __shared__ float red[256];
    int tid = threadIdx.x;
    float s = 0.0f;
    for (int i = tid; i < Bsz / 8; i += 256) s += g_partial[i];
    red[tid] = s;
    __syncthreads();
#pragma unroll
    for (int o = 128; o; o >>= 1) {
        if (tid < o) red[tid] += red[tid + o];
        __syncthreads();
    }
    if (tid == 0) out_loss[0] = 0.25f * red[0] * (1.0f / (float)Bsz);
}

// ============================================================================
// launch
// ============================================================================
extern "C" void kernel_launch(void* const* d_in, const int* in_sizes, int n_in,
                              void* d_out, int out_size) {
    const float* X = (const float*)d_in[0];
    const float* E = (const float*)d_in[1];
    float* out = (float*)d_out;

    const long long BD = (long long)Bsz * Dsz;
    long long osz = (long long)out_size;
    int w_loss = (osz >= BD + 1);
    int w_idx  = (osz >= BD + 1 + (long long)Bsz);
    int w_sca  = (osz >= BD + 1 + 2LL * (long long)Bsz);

    float* xq       = out;
    float* out_loss = out + BD;
    float* out_idx  = out + BD + 1;
    float* out_sca  = out + BD + 1 + Bsz;

    uint4* x3; uint4* e3;
    (void)cudaGetSymbolAddress((void**)&x3, X3u);
    (void)cudaGetSymbolAddress((void**)&e3, E3u);
    (void)cudaFuncSetAttribute(k_gemm_mma,
                               cudaFuncAttributeMaxDynamicSharedMemorySize, SMEM_G);

    k_rnorm<<<Nsz / 8, 256>>>(E);
    k_convert<<<(Bsz * 8) / 256, 256>>>(X, x3, Bsz);
    k_convert<<<(Nsz * 8) / 256, 256>>>(E, e3, Nsz);
    k_gemm_mma<<<Bsz / 128, 256, SMEM_G>>>(out_idx, w_idx);
    k_epilogue<<<Bsz / 8, 256>>>(X, E, xq, out_sca, w_sca);
    if (w_loss) k_loss<<<1, 256>>>(out_loss);
}